// round 12
// baseline (speedup 1.0000x reference)
#include <cuda_runtime.h>
#include <math.h>

// Problem constants
#define B_DIM 512
#define T_DIM 2048
#define C_DIM 64
#define JITTER 0.01f
#define TW_K (0.2f / 2048.0f)   // TW_SIGMA / T

// Precomputed time-warp table: .x = bitcast(i0), .y = frac
__device__ float2 g_warp_tab[T_DIM];

// ---------------------------------------------------------------------------
// Kernel 1: cumsum of warp_noise, normalize, compute (i0, frac) per t.
// One block of 256 threads; each thread scans 8 contiguous elements, then
// a Hillis-Steele scan over the 256 chunk totals.
// ---------------------------------------------------------------------------
__global__ void __launch_bounds__(256) warp_scan_kernel(const float* __restrict__ wn)
{
    __shared__ float csum[256];
    __shared__ float s_cs0;

    const int tid = threadIdx.x;

    // Sequential inclusive scan of this thread's 8-element chunk
    float v[8];
    float acc = 0.0f;
#pragma unroll
    for (int i = 0; i < 8; ++i) {
        acc += wn[tid * 8 + i] * TW_K;
        v[i] = acc;
    }
    csum[tid] = acc;
    if (tid == 0) s_cs0 = v[0];   // cumsum[0] = wn[0]*k
    __syncthreads();

    // Hillis-Steele inclusive scan over 256 chunk totals
#pragma unroll
    for (int off = 1; off < 256; off <<= 1) {
        float add = (tid >= off) ? csum[tid - off] : 0.0f;
        __syncthreads();
        csum[tid] += add;
        __syncthreads();
    }

    const float excl  = (tid > 0) ? csum[tid - 1] : 0.0f;
    const float total = csum[255];          // inclusive cumsum[T-1]
    const float cs0   = s_cs0;
    const float denom = (total - cs0) + 1e-8f;   // ref: warp[-1] read after -=warp[0]
    const float inv_denom = 1.0f / denom;

#pragma unroll
    for (int i = 0; i < 8; ++i) {
        int t = tid * 8 + i;
        float w  = (excl + v[i] - cs0) * inv_denom;       // normalized warp
        float tw = (float)t * (1.0f / 2047.0f) + w * 0.2f;
        tw = fminf(fmaxf(tw, 0.0f), 1.0f);
        float pos = tw * 2047.0f;
        int i0 = (int)floorf(pos);
        i0 = min(max(i0, 0), 2046);
        float2 e;
        e.x = __int_as_float(i0);
        e.y = pos - (float)i0;
        g_warp_tab[t] = e;
    }
}

// ---------------------------------------------------------------------------
// Kernel 2: fused jitter/gather-blend/rotate/scale-mask.
// Grid: B * (T/32) blocks of 512 threads. Each block handles 32 consecutive
// t rows of one batch b; each thread handles one float4 of one row (c4=0..15).
// Adjacent t rows gather overlapping input rows -> L1/L2 absorbs the 2x.
// ---------------------------------------------------------------------------
__global__ void __launch_bounds__(512) augment_kernel(
    const float* __restrict__ x,
    const float* __restrict__ noise,
    const float* __restrict__ scale_u,
    const float* __restrict__ angle_u,
    const float* __restrict__ chmask_u,
    float* __restrict__ out)
{
    const int tid = threadIdx.x;
    const int c4  = tid & 15;        // which float4 within the 64-channel row
    const int row = tid >> 4;        // 0..31, row within tile
    const int bid = blockIdx.x;
    const int b   = bid >> 6;        // T/32 = 64 tiles per batch
    const int tt  = bid & 63;
    const int t   = tt * 32 + row;

    const float2 wtab = g_warp_tab[t];
    const int    i0   = __float_as_int(wtab.x);
    const float  f    = wtab.y;
    const float scale = fmaf(__ldg(scale_u), 0.2f, 0.9f);   // 0.9 + u*0.2

    const size_t base = ((size_t)b * T_DIM + (size_t)i0) * C_DIM + (size_t)c4 * 4;

    float4 xa = *(const float4*)(x + base);
    float4 xb = *(const float4*)(x + base + C_DIM);
    float4 na = *(const float4*)(noise + base);
    float4 nb = *(const float4*)(noise + base + C_DIM);

    // y = x + 0.01*noise at both gather rows
    float4 ya, yb, r;
    ya.x = fmaf(na.x, JITTER, xa.x);
    ya.y = fmaf(na.y, JITTER, xa.y);
    ya.z = fmaf(na.z, JITTER, xa.z);
    ya.w = fmaf(na.w, JITTER, xa.w);
    yb.x = fmaf(nb.x, JITTER, xb.x);
    yb.y = fmaf(nb.y, JITTER, xb.y);
    yb.z = fmaf(nb.z, JITTER, xb.z);
    yb.w = fmaf(nb.w, JITTER, xb.w);

    // linear blend: (1-f)*ya + f*yb  ==  ya + f*(yb - ya)
    r.x = fmaf(f, yb.x - ya.x, ya.x);
    r.y = fmaf(f, yb.y - ya.y, ya.y);
    r.z = fmaf(f, yb.z - ya.z, ya.z);
    r.w = fmaf(f, yb.w - ya.w, ya.w);

    // rotate channels 0,1 by per-batch angle (only first float4 of each row)
    if (c4 == 0) {
        float ang = fmaf(__ldg(angle_u + b), 6.283185307179586f,
                         -3.141592653589793f);
        float sa, ca;
        sincosf(ang, &sa, &ca);
        float r0 = ca * r.x - sa * r.y;
        float r1 = sa * r.x + ca * r.y;
        r.x = r0;
        r.y = r1;
    }

    // channel mask folded with global scale (rotation/scale commute: linear)
    const int c = c4 * 4;
    float4 m;
    m.x = (__ldg(chmask_u + c + 0) > 0.1f) ? scale : 0.0f;
    m.y = (__ldg(chmask_u + c + 1) > 0.1f) ? scale : 0.0f;
    m.z = (__ldg(chmask_u + c + 2) > 0.1f) ? scale : 0.0f;
    m.w = (__ldg(chmask_u + c + 3) > 0.1f) ? scale : 0.0f;

    float4 o;
    o.x = r.x * m.x;
    o.y = r.y * m.y;
    o.z = r.z * m.z;
    o.w = r.w * m.w;

    const size_t obase = ((size_t)b * T_DIM + (size_t)t) * C_DIM + (size_t)c4 * 4;
    // Output is write-once and never re-read: stream it (evict-first),
    // keeping L2 capacity for the gather's 2x row-overlap on x/noise.
    __stcs((float4*)(out + obase), o);
}

// ---------------------------------------------------------------------------
// Launch
// ---------------------------------------------------------------------------
extern "C" void kernel_launch(void* const* d_in, const int* in_sizes, int n_in,
                              void* d_out, int out_size)
{
    const float* x        = (const float*)d_in[0];
    const float* noise    = (const float*)d_in[1];
    const float* scale_u  = (const float*)d_in[2];
    const float* warp_n   = (const float*)d_in[3];
    const float* angle_u  = (const float*)d_in[4];
    const float* chmask_u = (const float*)d_in[5];
    float* out = (float*)d_out;

    warp_scan_kernel<<<1, 256>>>(warp_n);
    augment_kernel<<<B_DIM * (T_DIM / 32), 512>>>(x, noise, scale_u, angle_u,
                                                  chmask_u, out);
}

// round 17
// speedup vs baseline: 1.1150x; 1.1150x over previous
#include <cuda_runtime.h>
#include <math.h>

// Problem constants
#define B_DIM 512
#define T_DIM 2048
#define C_DIM 64
#define JITTER 0.01f
#define TW_K (0.2f / 2048.0f)   // TW_SIGMA / T

// Precomputed tables (written by prologue kernel)
__device__ float2 g_warp_tab[T_DIM];   // .x = bitcast(i0), .y = frac
__device__ float  g_mask[C_DIM];       // chmask * global scale, folded
__device__ float2 g_rot[B_DIM];        // (cos, sin) per batch

// ---------------------------------------------------------------------------
// Kernel 1 (prologue): warp cumsum -> (i0, frac) table, plus folded
// mask*scale table and per-batch rotation (cos, sin).
// One block of 256 threads.
// ---------------------------------------------------------------------------
__global__ void __launch_bounds__(256) prologue_kernel(
    const float* __restrict__ wn,
    const float* __restrict__ scale_u,
    const float* __restrict__ angle_u,
    const float* __restrict__ chmask_u)
{
    __shared__ float csum[256];
    __shared__ float s_cs0;

    const int tid = threadIdx.x;

    // --- folded mask * scale table (64 entries) ---
    const float scale = fmaf(scale_u[0], 0.2f, 0.9f);   // 0.9 + u*0.2
    if (tid < C_DIM)
        g_mask[tid] = (chmask_u[tid] > 0.1f) ? scale : 0.0f;

    // --- per-batch rotation table (512 entries, 2 per thread) ---
#pragma unroll
    for (int i = 0; i < 2; ++i) {
        int bb = tid + i * 256;
        float ang = fmaf(angle_u[bb], 6.283185307179586f, -3.141592653589793f);
        float sa, ca;
        sincosf(ang, &sa, &ca);
        g_rot[bb] = make_float2(ca, sa);
    }

    // --- time-warp scan ---
    float v[8];
    float acc = 0.0f;
#pragma unroll
    for (int i = 0; i < 8; ++i) {
        acc += wn[tid * 8 + i] * TW_K;
        v[i] = acc;
    }
    csum[tid] = acc;
    if (tid == 0) s_cs0 = v[0];   // cumsum[0] = wn[0]*k
    __syncthreads();

#pragma unroll
    for (int off = 1; off < 256; off <<= 1) {
        float add = (tid >= off) ? csum[tid - off] : 0.0f;
        __syncthreads();
        csum[tid] += add;
        __syncthreads();
    }

    const float excl  = (tid > 0) ? csum[tid - 1] : 0.0f;
    const float total = csum[255];          // inclusive cumsum[T-1]
    const float cs0   = s_cs0;
    const float denom = (total - cs0) + 1e-8f;   // ref: warp[-1] read after -=warp[0]
    const float inv_denom = 1.0f / denom;

#pragma unroll
    for (int i = 0; i < 8; ++i) {
        int t = tid * 8 + i;
        float w  = (excl + v[i] - cs0) * inv_denom;       // normalized warp
        float tw = (float)t * (1.0f / 2047.0f) + w * 0.2f;
        tw = fminf(fmaxf(tw, 0.0f), 1.0f);
        float pos = tw * 2047.0f;
        int i0 = (int)floorf(pos);
        i0 = min(max(i0, 0), 2046);
        float2 e;
        e.x = __int_as_float(i0);
        e.y = pos - (float)i0;
        g_warp_tab[t] = e;
    }
}

// ---------------------------------------------------------------------------
// Kernel 2: fused jitter/gather-blend/rotate/mask.
// Grid: B * (T/64) blocks of 512 threads. Each block covers 64 consecutive
// t rows; each thread handles TWO float4s of one row (c4 and c4+8), giving
// 8 independent in-flight LDG.128s per thread (2x the MLP of the previous
// version, which profiled at DRAM=66.8% / issue=48.2% -> latency-limited).
// ---------------------------------------------------------------------------
__global__ void __launch_bounds__(512) augment_kernel(
    const float* __restrict__ x,
    const float* __restrict__ noise,
    float* __restrict__ out)
{
    const int tid = threadIdx.x;
    const int c4  = tid & 7;         // float4 slot 0..7 (also handles slot c4+8)
    const int row = tid >> 3;        // 0..63, row within tile
    const int bid = blockIdx.x;
    const int b   = bid >> 5;        // T/64 = 32 tiles per batch
    const int tt  = bid & 31;
    const int t   = tt * 64 + row;

    const float2 wtab = g_warp_tab[t];
    const int    i0   = __float_as_int(wtab.x);
    const float  f    = wtab.y;

    const size_t base = ((size_t)b * T_DIM + (size_t)i0) * C_DIM + (size_t)c4 * 4;

    // 8 independent 16B loads (2 col-slots x {row i0, row i0+1} x {x, noise})
    float4 xa0 = *(const float4*)(x + base);
    float4 xa1 = *(const float4*)(x + base + 32);
    float4 xb0 = *(const float4*)(x + base + C_DIM);
    float4 xb1 = *(const float4*)(x + base + C_DIM + 32);
    float4 na0 = *(const float4*)(noise + base);
    float4 na1 = *(const float4*)(noise + base + 32);
    float4 nb0 = *(const float4*)(noise + base + C_DIM);
    float4 nb1 = *(const float4*)(noise + base + C_DIM + 32);

    // y = x + 0.01*noise ; blend r = ya + f*(yb - ya)
    float4 r0, r1;
    {
        float4 ya, yb;
        ya.x = fmaf(na0.x, JITTER, xa0.x);  yb.x = fmaf(nb0.x, JITTER, xb0.x);
        ya.y = fmaf(na0.y, JITTER, xa0.y);  yb.y = fmaf(nb0.y, JITTER, xb0.y);
        ya.z = fmaf(na0.z, JITTER, xa0.z);  yb.z = fmaf(nb0.z, JITTER, xb0.z);
        ya.w = fmaf(na0.w, JITTER, xa0.w);  yb.w = fmaf(nb0.w, JITTER, xb0.w);
        r0.x = fmaf(f, yb.x - ya.x, ya.x);
        r0.y = fmaf(f, yb.y - ya.y, ya.y);
        r0.z = fmaf(f, yb.z - ya.z, ya.z);
        r0.w = fmaf(f, yb.w - ya.w, ya.w);
    }
    {
        float4 ya, yb;
        ya.x = fmaf(na1.x, JITTER, xa1.x);  yb.x = fmaf(nb1.x, JITTER, xb1.x);
        ya.y = fmaf(na1.y, JITTER, xa1.y);  yb.y = fmaf(nb1.y, JITTER, xb1.y);
        ya.z = fmaf(na1.z, JITTER, xa1.z);  yb.z = fmaf(nb1.z, JITTER, xb1.z);
        ya.w = fmaf(na1.w, JITTER, xa1.w);  yb.w = fmaf(nb1.w, JITTER, xb1.w);
        r1.x = fmaf(f, yb.x - ya.x, ya.x);
        r1.y = fmaf(f, yb.y - ya.y, ya.y);
        r1.z = fmaf(f, yb.z - ya.z, ya.z);
        r1.w = fmaf(f, yb.w - ya.w, ya.w);
    }

    // rotate channels 0,1 by per-batch angle (only c4==0 touches them)
    if (c4 == 0) {
        const float2 rot = g_rot[b];    // (cos, sin), precomputed
        float t0 = rot.x * r0.x - rot.y * r0.y;
        float t1 = rot.y * r0.x + rot.x * r0.y;
        r0.x = t0;
        r0.y = t1;
    }

    // folded mask*scale (L1-resident 256B table)
    const float4 m0 = *(const float4*)(g_mask + c4 * 4);
    const float4 m1 = *(const float4*)(g_mask + c4 * 4 + 32);

    float4 o0, o1;
    o0.x = r0.x * m0.x;  o0.y = r0.y * m0.y;
    o0.z = r0.z * m0.z;  o0.w = r0.w * m0.w;
    o1.x = r1.x * m1.x;  o1.y = r1.y * m1.y;
    o1.z = r1.z * m1.z;  o1.w = r1.w * m1.w;

    const size_t obase = ((size_t)b * T_DIM + (size_t)t) * C_DIM + (size_t)c4 * 4;
    // Output is write-once: stream (evict-first), keep L2 for the gather overlap.
    __stcs((float4*)(out + obase), o0);
    __stcs((float4*)(out + obase + 32), o1);
}

// ---------------------------------------------------------------------------
// Launch
// ---------------------------------------------------------------------------
extern "C" void kernel_launch(void* const* d_in, const int* in_sizes, int n_in,
                              void* d_out, int out_size)
{
    const float* x        = (const float*)d_in[0];
    const float* noise    = (const float*)d_in[1];
    const float* scale_u  = (const float*)d_in[2];
    const float* warp_n   = (const float*)d_in[3];
    const float* angle_u  = (const float*)d_in[4];
    const float* chmask_u = (const float*)d_in[5];
    float* out = (float*)d_out;

    prologue_kernel<<<1, 256>>>(warp_n, scale_u, angle_u, chmask_u);
    augment_kernel<<<B_DIM * (T_DIM / 64), 512>>>(x, noise, out);
}